// round 2
// baseline (speedup 1.0000x reference)
#include <cuda_runtime.h>
#include <math.h>

#define NLAYER 6
#define NH     16
#define DHEAD  96
#define DIMD   1024
#define INNER  1536
#define DFF    4096
#define NLAT   128
#define BT     32                 /* b*T sites                */
#define NMED   1024               /* media tokens per site    */
#define XROWS  (BT*NMED)          /* 32768 media rows total   */
#define RL     (BT*NLAT)          /* 4096 latent rows total   */
#define NKV    (NMED+NLAT)        /* 1152 KV per site         */
#define KV2    (2*INNER)          /* 3072 */

// ---------------- scratch (device globals; no allocation) ----------------
__device__ float g_lat[(size_t)RL*DIMD];        // current latents    16 MB
__device__ float g_lm [(size_t)RL*DIMD];        // LN(latents)        16 MB
__device__ float g_xm [(size_t)XROWS*DIMD];     // LN(media)         128 MB
__device__ float g_q  [(size_t)RL*INNER];       // queries            24 MB
__device__ float g_kvl[(size_t)RL*KV2];         // latent K|V         48 MB
__device__ float g_kvx[(size_t)XROWS*KV2];      // media  K|V        402 MB
__device__ float g_o  [(size_t)RL*INNER];       // attention out      24 MB
__device__ float g_s  [(size_t)BT*NH*NLAT*NKV]; // scores/probs      302 MB
__device__ float g_h  [(size_t)RL*DFF];         // FF hidden          64 MB

// ---------------- broadcast latents to all 32 (b,T) sites ----------------
__global__ void bcast_kernel(const float* __restrict__ lat) {
    int i = blockIdx.x * 256 + threadIdx.x;
    int row = i >> 10;
    int col = i & 1023;
    g_lat[i] = lat[((row & (NLAT-1)) << 10) + col];
}

// ---------------- LayerNorm: one block per row of 1024 -------------------
__global__ void ln_kernel(const float* __restrict__ in,
                          const float* __restrict__ gg,
                          const float* __restrict__ bb,
                          float* __restrict__ out) {
    __shared__ float red[256];
    int row = blockIdx.x, t = threadIdx.x;
    const float* x = in + (size_t)row * DIMD;
    float v[4]; float s = 0.f;
    #pragma unroll
    for (int i = 0; i < 4; i++) { v[i] = x[t + 256*i]; s += v[i]; }
    red[t] = s; __syncthreads();
    #pragma unroll
    for (int o = 128; o > 0; o >>= 1) { if (t < o) red[t] += red[t+o]; __syncthreads(); }
    float mu = red[0] * (1.f/DIMD);
    __syncthreads();
    float s2 = 0.f;
    #pragma unroll
    for (int i = 0; i < 4; i++) { float d = v[i]-mu; s2 += d*d; }
    red[t] = s2; __syncthreads();
    #pragma unroll
    for (int o = 128; o > 0; o >>= 1) { if (t < o) red[t] += red[t+o]; __syncthreads(); }
    float inv = rsqrtf(red[0]*(1.f/DIMD) + 1e-5f);
    float* y = out + (size_t)row * DIMD;
    #pragma unroll
    for (int i = 0; i < 4; i++) { int c = t + 256*i; y[c] = (v[i]-mu)*inv*gg[c] + bb[c]; }
}

// ---------------- fp32 SGEMM, 128x128x16 tiles, 8x8 per thread -----------
// EPI: 0 = C = alpha*A@B ; 1 = C += A@B ; 2 = C = gelu_exact(A@B)
template<int EPI>
__global__ void __launch_bounds__(256)
sgemm(const float* __restrict__ A, const float* __restrict__ B,
      float* __restrict__ C, int M, int N, int K, float alpha) {
    __shared__ float As[16][129];   // padded (transposed A tile)
    __shared__ float Bs[16][128];
    int t  = threadIdx.x;
    int tx = t & 15, ty = t >> 4;
    int bx = blockIdx.x, by = blockIdx.y;

    float acc[8][8];
    #pragma unroll
    for (int i = 0; i < 8; i++)
        #pragma unroll
        for (int j = 0; j < 8; j++) acc[i][j] = 0.f;

    int aRow = t >> 2;            // 0..63 (and +64)
    int aCol = (t & 3) * 4;
    int bRow = t >> 5;            // 0..7  (and +8)
    int bCol = (t & 31) * 4;
    const float* Ablk = A + (size_t)(by*128) * K;
    const float* Bblk = B + bx*128;

    for (int k0 = 0; k0 < K; k0 += 16) {
        #pragma unroll
        for (int hh = 0; hh < 2; hh++) {
            int r = aRow + hh*64;
            int gr = by*128 + r;
            float4 va = make_float4(0.f,0.f,0.f,0.f);
            if (gr < M) va = *(const float4*)(Ablk + (size_t)r*K + k0 + aCol);
            As[aCol+0][r] = va.x; As[aCol+1][r] = va.y;
            As[aCol+2][r] = va.z; As[aCol+3][r] = va.w;
        }
        #pragma unroll
        for (int hh = 0; hh < 2; hh++) {
            int r = bRow + hh*8;
            *(float4*)&Bs[r][bCol] = *(const float4*)(Bblk + (size_t)(k0+r)*N + bCol);
        }
        __syncthreads();
        #pragma unroll
        for (int kk = 0; kk < 16; kk++) {
            float ra[8], rb[8];
            #pragma unroll
            for (int i = 0; i < 8; i++) ra[i] = As[kk][ty*8 + i];
            #pragma unroll
            for (int j = 0; j < 4; j++) { rb[j] = Bs[kk][tx*4 + j]; rb[j+4] = Bs[kk][64 + tx*4 + j]; }
            #pragma unroll
            for (int i = 0; i < 8; i++)
                #pragma unroll
                for (int j = 0; j < 8; j++) acc[i][j] += ra[i]*rb[j];
        }
        __syncthreads();
    }

    #pragma unroll
    for (int i = 0; i < 8; i++) {
        int gr = by*128 + ty*8 + i;
        if (gr >= M) continue;
        float* crow = C + (size_t)gr*N + bx*128;
        #pragma unroll
        for (int j = 0; j < 8; j++) {
            int cc = (j < 4) ? (tx*4 + j) : (64 + tx*4 + j - 4);
            float val = acc[i][j] * alpha;
            if (EPI == 1) val += crow[cc];
            if (EPI == 2) val = 0.5f * val * (1.0f + erff(val * 0.70710678118654752f));
            crow[cc] = val;
        }
    }
}

// ---- scores: block = (bt, h, jt); S[128 x 128-tile] = Q K^T + bias ------
__global__ void __launch_bounds__(256)
scores_kernel(const float* __restrict__ vmask) {
    int bt = blockIdx.x, h = blockIdx.y, jt = blockIdx.z;
    int b  = bt >> 2;                       // T = 4
    int j0 = jt * 128;
    __shared__ float Qs[32][129];
    __shared__ float Ks[32][129];
    int t = threadIdx.x, tx = t & 15, ty = t >> 4;

    float acc[8][8];
    #pragma unroll
    for (int i = 0; i < 8; i++)
        #pragma unroll
        for (int j = 0; j < 8; j++) acc[i][j] = 0.f;

    for (int dc = 0; dc < DHEAD; dc += 32) {
        for (int idx = t; idx < 128*32; idx += 256) {
            int i = idx >> 5, d = idx & 31;
            Qs[d][i] = g_q[((size_t)(bt*NLAT + i))*INNER + h*DHEAD + dc + d];
        }
        for (int idx = t; idx < 128*32; idx += 256) {
            int jj = idx >> 5, d = idx & 31;
            int j = j0 + jj;
            float kv = (j < NMED)
                ? g_kvx[((size_t)(bt*NMED + j))*KV2 + h*DHEAD + dc + d]
                : g_kvl[((size_t)(bt*NLAT + (j - NMED)))*KV2 + h*DHEAD + dc + d];
            Ks[d][jj] = kv;
        }
        __syncthreads();
        #pragma unroll 8
        for (int d = 0; d < 32; d++) {
            float ra[8], rb[8];
            #pragma unroll
            for (int i = 0; i < 8; i++) ra[i] = Qs[d][ty*8 + i];
            #pragma unroll
            for (int j = 0; j < 4; j++) { rb[j] = Ks[d][tx*4 + j]; rb[j+4] = Ks[d][64 + tx*4 + j]; }
            #pragma unroll
            for (int i = 0; i < 8; i++)
                #pragma unroll
                for (int j = 0; j < 8; j++) acc[i][j] += ra[i]*rb[j];
        }
        __syncthreads();
    }

    size_t base = ((size_t)(bt*NH + h)) * NLAT;
    #pragma unroll
    for (int i = 0; i < 8; i++) {
        int row = ty*8 + i;
        #pragma unroll
        for (int j = 0; j < 8; j++) {
            int cc = (j < 4) ? (tx*4 + j) : (64 + tx*4 + j - 4);
            int jg = j0 + cc;
            float v = acc[i][j];
            if (jg < NMED && !(vmask[b*NMED + jg] > 0.f)) v = -INFINITY;
            g_s[(base + row)*NKV + jg] = v;
        }
    }
}

// ---------------- softmax over 1152 KV, one block per row ----------------
__global__ void softmax_kernel() {
    size_t row = blockIdx.x;
    float* s = g_s + row * (size_t)NKV;
    int t = threadIdx.x;
    __shared__ float red[256];
    float m = -INFINITY;
    for (int j = t; j < NKV; j += 256) m = fmaxf(m, s[j]);
    red[t] = m; __syncthreads();
    #pragma unroll
    for (int o = 128; o > 0; o >>= 1) { if (t < o) red[t] = fmaxf(red[t], red[t+o]); __syncthreads(); }
    m = red[0]; __syncthreads();
    float e[5]; int c = 0; float sum = 0.f;
    for (int j = t; j < NKV; j += 256) { e[c] = expf(s[j] - m); sum += e[c]; c++; }
    red[t] = sum; __syncthreads();
    #pragma unroll
    for (int o = 128; o > 0; o >>= 1) { if (t < o) red[t] += red[t+o]; __syncthreads(); }
    float inv = 1.f / red[0];
    c = 0;
    for (int j = t; j < NKV; j += 256) { s[j] = e[c] * inv; c++; }
}

// ---------------- O = P V : one block per (bt, h) ------------------------
__global__ void __launch_bounds__(256)
av_kernel() {
    int bt = blockIdx.x, h = blockIdx.y;
    __shared__ float Ps[32][133];
    __shared__ float Vs[32][96];
    int t = threadIdx.x, tx = t & 15, ty = t >> 4;

    float acc[8][6];
    #pragma unroll
    for (int i = 0; i < 8; i++)
        #pragma unroll
        for (int d = 0; d < 6; d++) acc[i][d] = 0.f;

    size_t prow0 = (size_t)(bt*NH + h) * NLAT;
    for (int jc = 0; jc < NKV; jc += 32) {          // 1152 = 36*32, no tail
        for (int idx = t; idx < 128*32; idx += 256) {
            int i = idx >> 5, jj = idx & 31;
            Ps[jj][i] = g_s[(prow0 + i)*NKV + jc + jj];
        }
        for (int idx = t; idx < 32*96; idx += 256) {
            int jj = idx / 96, d = idx % 96;
            int j = jc + jj;
            float vv = (j < NMED)
                ? g_kvx[((size_t)(bt*NMED + j))*KV2 + INNER + h*DHEAD + d]
                : g_kvl[((size_t)(bt*NLAT + (j - NMED)))*KV2 + INNER + h*DHEAD + d];
            Vs[jj][d] = vv;
        }
        __syncthreads();
        #pragma unroll 8
        for (int jj = 0; jj < 32; jj++) {
            float ra[8], rb[6];
            #pragma unroll
            for (int i = 0; i < 8; i++) ra[i] = Ps[jj][ty*8 + i];
            #pragma unroll
            for (int d = 0; d < 6; d++) rb[d] = Vs[jj][tx + 16*d];
            #pragma unroll
            for (int i = 0; i < 8; i++)
                #pragma unroll
                for (int d = 0; d < 6; d++) acc[i][d] += ra[i]*rb[d];
        }
        __syncthreads();
    }

    #pragma unroll
    for (int i = 0; i < 8; i++)
        #pragma unroll
        for (int d = 0; d < 6; d++)
            g_o[((size_t)(bt*NLAT + ty*8 + i))*INNER + h*DHEAD + tx + 16*d] = acc[i][d];
}

// ---------------- host orchestration (graph-capturable) ------------------
extern "C" void kernel_launch(void* const* d_in, const int* in_sizes, int n_in,
                              void* d_out, int out_size) {
    (void)in_sizes; (void)n_in; (void)out_size;
    const float* x       = (const float*)d_in[0];
    const float* vmask   = (const float*)d_in[1];
    const float* latents = (const float*)d_in[2];
    const float* ln_m_g  = (const float*)d_in[3];
    const float* ln_m_b  = (const float*)d_in[4];
    const float* ln_l_g  = (const float*)d_in[5];
    const float* ln_l_b  = (const float*)d_in[6];
    const float* q_w     = (const float*)d_in[7];
    const float* kv_w    = (const float*)d_in[8];
    const float* out_w   = (const float*)d_in[9];
    const float* ff_ln_g = (const float*)d_in[10];
    const float* ff_ln_b = (const float*)d_in[11];
    const float* ff_w1   = (const float*)d_in[12];
    const float* ff_w2   = (const float*)d_in[13];
    const float* fn_g    = (const float*)d_in[14];
    const float* fn_b    = (const float*)d_in[15];
    float* out = (float*)d_out;

    float *p_lat, *p_lm, *p_xm, *p_q, *p_kvl, *p_kvx, *p_o, *p_h;
    cudaGetSymbolAddress((void**)&p_lat, g_lat);
    cudaGetSymbolAddress((void**)&p_lm,  g_lm);
    cudaGetSymbolAddress((void**)&p_xm,  g_xm);
    cudaGetSymbolAddress((void**)&p_q,   g_q);
    cudaGetSymbolAddress((void**)&p_kvl, g_kvl);
    cudaGetSymbolAddress((void**)&p_kvx, g_kvx);
    cudaGetSymbolAddress((void**)&p_o,   g_o);
    cudaGetSymbolAddress((void**)&p_h,   g_h);

    const float scale = 1.0f / sqrtf((float)DHEAD);

    bcast_kernel<<<RL*DIMD/256, 256>>>(latents);

    for (int l = 0; l < NLAYER; l++) {
        ln_kernel<<<XROWS, 256>>>(x,     ln_m_g + l*DIMD, ln_m_b + l*DIMD, p_xm);
        ln_kernel<<<RL,    256>>>(p_lat, ln_l_g + l*DIMD, ln_l_b + l*DIMD, p_lm);

        sgemm<0><<<dim3(INNER/128, RL/128),    256>>>(p_lm, q_w  + (size_t)l*DIMD*INNER, p_q,   RL,    INNER, DIMD, scale);
        sgemm<0><<<dim3(KV2/128,   RL/128),    256>>>(p_lm, kv_w + (size_t)l*DIMD*KV2,   p_kvl, RL,    KV2,   DIMD, 1.f);
        sgemm<0><<<dim3(KV2/128,   XROWS/128), 256>>>(p_xm, kv_w + (size_t)l*DIMD*KV2,   p_kvx, XROWS, KV2,   DIMD, 1.f);

        scores_kernel<<<dim3(BT, NH, NKV/128), 256>>>(vmask);
        softmax_kernel<<<BT*NH*NLAT, 256>>>();
        av_kernel<<<dim3(BT, NH), 256>>>();

        sgemm<1><<<dim3(DIMD/128, RL/128), 256>>>(p_o, out_w + (size_t)l*INNER*DIMD, p_lat, RL, DIMD, INNER, 1.f);

        ln_kernel<<<RL, 256>>>(p_lat, ff_ln_g + l*DIMD, ff_ln_b + l*DIMD, p_lm);
        sgemm<2><<<dim3(DFF/128,  RL/128), 256>>>(p_lm, ff_w1 + (size_t)l*DIMD*DFF, p_h,   RL, DFF,  DIMD, 1.f);
        sgemm<1><<<dim3(DIMD/128, RL/128), 256>>>(p_h,  ff_w2 + (size_t)l*DFF*DIMD, p_lat, RL, DIMD, DFF,  1.f);
    }

    ln_kernel<<<RL, 256>>>(p_lat, fn_g, fn_b, out);
}

// round 6
// speedup vs baseline: 1.5442x; 1.5442x over previous
#include <cuda_runtime.h>
#include <math.h>
#include <stdint.h>

#define NLAYER 6
#define NH     16
#define DHEAD  96
#define DIMD   1024
#define INNER  1536
#define DFF    4096
#define NLAT   128
#define BT     32                 /* b*T sites                */
#define NMED   1024               /* media tokens per site    */
#define XROWS  (BT*NMED)          /* 32768 media rows total   */
#define RL     (BT*NLAT)          /* 4096 latent rows total   */
#define NKV    (NMED+NLAT)        /* 1152 KV per site         */
#define KV2    (2*INNER)          /* 3072 */

// ---------------- scratch (device globals; no allocation) ----------------
__device__ float g_lat[(size_t)RL*DIMD];
__device__ float g_lm [(size_t)RL*DIMD];
__device__ float g_xm [(size_t)XROWS*DIMD];
__device__ float g_q  [(size_t)RL*INNER];
__device__ float g_kvl[(size_t)RL*KV2];
__device__ float g_kvx[(size_t)XROWS*KV2];
__device__ float g_o  [(size_t)RL*INNER];
__device__ float g_s  [(size_t)BT*NH*NLAT*NKV];
__device__ float g_h  [(size_t)RL*DFF];
// transposed weights (B operands K-major: [N][K])
__device__ float g_qwT [(size_t)NLAYER*INNER*DIMD];
__device__ float g_kvT [(size_t)NLAYER*KV2*DIMD];
__device__ float g_outT[(size_t)NLAYER*DIMD*INNER];
__device__ float g_ff1T[(size_t)NLAYER*DFF*DIMD];
__device__ float g_ff2T[(size_t)NLAYER*DIMD*DFF];

// ======================= PTX helpers =====================================
__device__ __forceinline__ uint32_t smem_u32(const void* p) {
    uint32_t r;
    asm("{ .reg .u64 t; cvta.to.shared.u64 t, %1; cvt.u32.u64 %0, t; }"
        : "=r"(r) : "l"(p));
    return r;
}

__device__ __forceinline__ void ldsm4(uint32_t* r, uint32_t a) {
    asm volatile("ldmatrix.sync.aligned.m8n8.x4.shared.b16 {%0,%1,%2,%3}, [%4];"
        : "=r"(r[0]), "=r"(r[1]), "=r"(r[2]), "=r"(r[3]) : "r"(a));
}
__device__ __forceinline__ void ldsm2(uint32_t* r, uint32_t a) {
    asm volatile("ldmatrix.sync.aligned.m8n8.x2.shared.b16 {%0,%1}, [%2];"
        : "=r"(r[0]), "=r"(r[1]) : "r"(a));
}
__device__ __forceinline__ void mma16816(float* c, const uint32_t* a, const uint32_t* b) {
    asm volatile("mma.sync.aligned.m16n8k16.row.col.f32.bf16.bf16.f32 "
        "{%0,%1,%2,%3}, {%4,%5,%6,%7}, {%8,%9}, {%0,%1,%2,%3};"
        : "+f"(c[0]), "+f"(c[1]), "+f"(c[2]), "+f"(c[3])
        : "r"(a[0]), "r"(a[1]), "r"(a[2]), "r"(a[3]), "r"(b[0]), "r"(b[1]));
}

// ======================= bf16x3 tensor-core GEMM =========================
// C[M,N] = epi(alpha * A[M,K] @ Bt[N,K]^T).  M,N multiples of 128; K of 32.
// EPI: 0 = alpha* ; 1 = C += ; 2 = gelu_exact
// SMEM stage: Ahi/Alo/Bhi/Blo, each 128 rows x 32 bf16, row stride 80 B.
#define ROWB   80
#define T_AHI  0
#define T_ALO  10240
#define T_BHI  20480
#define T_BLO  30720
#define STGSZ  40960
#define SMEM_TG (2*STGSZ)

template<int EPI>
__global__ void __launch_bounds__(256, 1)
tgemm(const float* __restrict__ A, const float* __restrict__ Bt,
      float* __restrict__ C, int M, int N, int K, float alpha) {
    extern __shared__ char smem[];
    const uint32_t sb = smem_u32(smem);
    const int t = threadIdx.x;
    const int lane = t & 31, wid = t >> 5;
    const int wm = (wid >> 2) * 64;        // 2 warp-rows
    const int wn = (wid & 3) * 32;         // 4 warp-cols
    const int m0 = blockIdx.y * 128, n0 = blockIdx.x * 128;

    const float* Ab = A  + (size_t)m0 * K;
    const float* Bb = Bt + (size_t)n0 * K;

    float acc[4][4][4];
    #pragma unroll
    for (int i = 0; i < 4; i++)
        #pragma unroll
        for (int j = 0; j < 4; j++)
            #pragma unroll
            for (int r = 0; r < 4; r++) acc[i][j][r] = 0.f;

    const int nch = K / 32;

    auto stage = [&](int c, int buf) {
        char* st = smem + buf * STGSZ;
        #pragma unroll
        for (int j = 0; j < 4; j++) {
            int idx = t + 256 * j;
            int row = idx >> 3, q = idx & 7;
            // ---- A ----
            float4 v = *(const float4*)(Ab + (size_t)row * K + c * 32 + q * 4);
            uint32_t h01 = __byte_perm(__float_as_uint(v.x), __float_as_uint(v.y), 0x7632);
            uint32_t h23 = __byte_perm(__float_as_uint(v.z), __float_as_uint(v.w), 0x7632);
            float lx = v.x - __uint_as_float(__float_as_uint(v.x) & 0xFFFF0000u);
            float ly = v.y - __uint_as_float(__float_as_uint(v.y) & 0xFFFF0000u);
            float lz = v.z - __uint_as_float(__float_as_uint(v.z) & 0xFFFF0000u);
            float lw = v.w - __uint_as_float(__float_as_uint(v.w) & 0xFFFF0000u);
            uint32_t l01, l23;
            asm("cvt.rn.bf16x2.f32 %0, %1, %2;" : "=r"(l01) : "f"(ly), "f"(lx));
            asm("cvt.rn.bf16x2.f32 %0, %1, %2;" : "=r"(l23) : "f"(lw), "f"(lz));
            *(uint2*)(st + T_AHI + row * ROWB + q * 8) = make_uint2(h01, h23);
            *(uint2*)(st + T_ALO + row * ROWB + q * 8) = make_uint2(l01, l23);
            // ---- B ----
            v = *(const float4*)(Bb + (size_t)row * K + c * 32 + q * 4);
            h01 = __byte_perm(__float_as_uint(v.x), __float_as_uint(v.y), 0x7632);
            h23 = __byte_perm(__float_as_uint(v.z), __float_as_uint(v.w), 0x7632);
            lx = v.x - __uint_as_float(__float_as_uint(v.x) & 0xFFFF0000u);
            ly = v.y - __uint_as_float(__float_as_uint(v.y) & 0xFFFF0000u);
            lz = v.z - __uint_as_float(__float_as_uint(v.z) & 0xFFFF0000u);
            lw = v.w - __uint_as_float(__float_as_uint(v.w) & 0xFFFF0000u);
            asm("cvt.rn.bf16x2.f32 %0, %1, %2;" : "=r"(l01) : "f"(ly), "f"(lx));
            asm("cvt.rn.bf16x2.f32 %0, %1, %2;" : "=r"(l23) : "f"(lw), "f"(lz));
            *(uint2*)(st + T_BHI + row * ROWB + q * 8) = make_uint2(h01, h23);
            *(uint2*)(st + T_BLO + row * ROWB + q * 8) = make_uint2(l01, l23);
        }
    };

    // fragment addressing (constant per thread)
    const int arow  = wm + (lane & 7) + ((lane >> 3) & 1) * 8;
    const int akoff = ((lane >> 4) & 1) * 16;
    const int brow  = wn + (lane & 7);
    const int bkoff = ((lane >> 3) & 1) * 16;

    stage(0, 0);
    __syncthreads();

    for (int c = 0; c < nch; c++) {
        if (c + 1 < nch) stage(c + 1, (c + 1) & 1);
        const uint32_t base = sb + (c & 1) * STGSZ;
        #pragma unroll
        for (int ks = 0; ks < 2; ks++) {
            uint32_t ah[4][4], al[4][4], bh[4][2], bl[4][2];
            #pragma unroll
            for (int mt = 0; mt < 4; mt++) {
                uint32_t ad = base + (uint32_t)(arow + mt * 16) * ROWB + ks * 32 + akoff;
                ldsm4(ah[mt], ad + T_AHI);
                ldsm4(al[mt], ad + T_ALO);
            }
            #pragma unroll
            for (int nt = 0; nt < 4; nt++) {
                uint32_t bd = base + (uint32_t)(brow + nt * 8) * ROWB + ks * 32 + bkoff;
                ldsm2(bh[nt], bd + T_BHI);
                ldsm2(bl[nt], bd + T_BLO);
            }
            #pragma unroll
            for (int mt = 0; mt < 4; mt++)
                #pragma unroll
                for (int nt = 0; nt < 4; nt++) {
                    mma16816(acc[mt][nt], ah[mt], bh[nt]);
                    mma16816(acc[mt][nt], ah[mt], bl[nt]);
                    mma16816(acc[mt][nt], al[mt], bh[nt]);
                }
        }
        __syncthreads();
    }

    // ---------------- epilogue ----------------
    const int rl = lane >> 2;                 // 0..7
    const int cl = (lane & 3) * 2;            // 0,2,4,6
    #pragma unroll
    for (int mt = 0; mt < 4; mt++) {
        #pragma unroll
        for (int nt = 0; nt < 4; nt++) {
            int gr = m0 + wm + mt * 16 + rl;
            int gc = n0 + wn + nt * 8 + cl;
            float* p0 = C + (size_t)gr * N + gc;
            float* p1 = C + (size_t)(gr + 8) * N + gc;
            float2 v0 = make_float2(acc[mt][nt][0] * alpha, acc[mt][nt][1] * alpha);
            float2 v1 = make_float2(acc[mt][nt][2] * alpha, acc[mt][nt][3] * alpha);
            if (EPI == 1) {
                float2 c0 = *(float2*)p0, c1 = *(float2*)p1;
                v0.x += c0.x; v0.y += c0.y; v1.x += c1.x; v1.y += c1.y;
            }
            if (EPI == 2) {
                v0.x = 0.5f * v0.x * (1.0f + erff(v0.x * 0.70710678118654752f));
                v0.y = 0.5f * v0.y * (1.0f + erff(v0.y * 0.70710678118654752f));
                v1.x = 0.5f * v1.x * (1.0f + erff(v1.x * 0.70710678118654752f));
                v1.y = 0.5f * v1.y * (1.0f + erff(v1.y * 0.70710678118654752f));
            }
            *(float2*)p0 = v0;
            *(float2*)p1 = v1;
        }
    }
}

// ---------------- weight transpose: [R][C] -> [C][R], z = layer ----------
__global__ void transpose_kernel(const float* __restrict__ src,
                                 float* __restrict__ dst, int R, int Ccols) {
    __shared__ float tile[32][33];
    size_t zoff = (size_t)blockIdx.z * R * Ccols;
    int r0 = blockIdx.y * 32, c0 = blockIdx.x * 32;
    int tx = threadIdx.x, ty = threadIdx.y;
    #pragma unroll
    for (int i = ty; i < 32; i += 8)
        tile[i][tx] = src[zoff + (size_t)(r0 + i) * Ccols + c0 + tx];
    __syncthreads();
    #pragma unroll
    for (int i = ty; i < 32; i += 8)
        dst[zoff + (size_t)(c0 + i) * R + r0 + tx] = tile[tx][i];
}

// ---------------- broadcast latents --------------------------------------
__global__ void bcast_kernel(const float* __restrict__ lat) {
    int i = blockIdx.x * 256 + threadIdx.x;
    int row = i >> 10;
    int col = i & 1023;
    g_lat[i] = lat[((row & (NLAT-1)) << 10) + col];
}

// ---------------- LayerNorm ----------------------------------------------
__global__ void ln_kernel(const float* __restrict__ in,
                          const float* __restrict__ gg,
                          const float* __restrict__ bb,
                          float* __restrict__ out) {
    __shared__ float red[256];
    int row = blockIdx.x, t = threadIdx.x;
    const float* x = in + (size_t)row * DIMD;
    float v[4]; float s = 0.f;
    #pragma unroll
    for (int i = 0; i < 4; i++) { v[i] = x[t + 256*i]; s += v[i]; }
    red[t] = s; __syncthreads();
    #pragma unroll
    for (int o = 128; o > 0; o >>= 1) { if (t < o) red[t] += red[t+o]; __syncthreads(); }
    float mu = red[0] * (1.f/DIMD);
    __syncthreads();
    float s2 = 0.f;
    #pragma unroll
    for (int i = 0; i < 4; i++) { float d = v[i]-mu; s2 += d*d; }
    red[t] = s2; __syncthreads();
    #pragma unroll
    for (int o = 128; o > 0; o >>= 1) { if (t < o) red[t] += red[t+o]; __syncthreads(); }
    float inv = rsqrtf(red[0]*(1.f/DIMD) + 1e-5f);
    float* y = out + (size_t)row * DIMD;
    #pragma unroll
    for (int i = 0; i < 4; i++) { int c = t + 256*i; y[c] = (v[i]-mu)*inv*gg[c] + bb[c]; }
}

// ---- scores: block = (bt, h, jt); S[128 x 128-tile] = Q K^T + bias ------
__global__ void __launch_bounds__(256)
scores_kernel(const float* __restrict__ vmask) {
    int bt = blockIdx.x, h = blockIdx.y, jt = blockIdx.z;
    int b  = bt >> 2;                       // T = 4
    int j0 = jt * 128;
    __shared__ float Qs[32][129];
    __shared__ float Ks[32][129];
    int t = threadIdx.x, tx = t & 15, ty = t >> 4;

    float acc[8][8];
    #pragma unroll
    for (int i = 0; i < 8; i++)
        #pragma unroll
        for (int j = 0; j < 8; j++) acc[i][j] = 0.f;

    for (int dc = 0; dc < DHEAD; dc += 32) {
        for (int idx = t; idx < 128*32; idx += 256) {
            int i = idx >> 5, d = idx & 31;
            Qs[d][i] = g_q[((size_t)(bt*NLAT + i))*INNER + h*DHEAD + dc + d];
        }
        for (int idx = t; idx < 128*32; idx += 256) {
            int jj = idx >> 5, d = idx & 31;
            int j = j0 + jj;
            float kv = (j < NMED)
                ? g_kvx[((size_t)(bt*NMED + j))*KV2 + h*DHEAD + dc + d]
                : g_kvl[((size_t)(bt*NLAT + (j - NMED)))*KV2 + h*DHEAD + dc + d];
            Ks[d][jj] = kv;
        }
        __syncthreads();
        #pragma unroll 8
        for (int d = 0; d < 32; d++) {
            float ra[8], rb[8];
            #pragma unroll
            for (int i = 0; i < 8; i++) ra[i] = Qs[d][ty*8 + i];
            #pragma unroll
            for (int j = 0; j < 4; j++) { rb[j] = Ks[d][tx*4 + j]; rb[j+4] = Ks[d][64 + tx*4 + j]; }
            #pragma unroll
            for (int i = 0; i < 8; i++)
                #pragma unroll
                for (int j = 0; j < 8; j++) acc[i][j] += ra[i]*rb[j];
        }
        __syncthreads();
    }

    size_t base = ((size_t)(bt*NH + h)) * NLAT;
    #pragma unroll
    for (int i = 0; i < 8; i++) {
        int row = ty*8 + i;
        #pragma unroll
        for (int j = 0; j < 8; j++) {
            int cc = (j < 4) ? (tx*4 + j) : (64 + tx*4 + j - 4);
            int jg = j0 + cc;
            float v = acc[i][j];
            if (jg < NMED && !(vmask[b*NMED + jg] > 0.f)) v = -INFINITY;
            g_s[(base + row)*NKV + jg] = v;
        }
    }
}

// ---------------- softmax over 1152 KV -----------------------------------
__global__ void softmax_kernel() {
    size_t row = blockIdx.x;
    float* s = g_s + row * (size_t)NKV;
    int t = threadIdx.x;
    __shared__ float red[256];
    float m = -INFINITY;
    for (int j = t; j < NKV; j += 256) m = fmaxf(m, s[j]);
    red[t] = m; __syncthreads();
    #pragma unroll
    for (int o = 128; o > 0; o >>= 1) { if (t < o) red[t] = fmaxf(red[t], red[t+o]); __syncthreads(); }
    m = red[0]; __syncthreads();
    float e[5]; int c = 0; float sum = 0.f;
    for (int j = t; j < NKV; j += 256) { e[c] = expf(s[j] - m); sum += e[c]; c++; }
    red[t] = sum; __syncthreads();
    #pragma unroll
    for (int o = 128; o > 0; o >>= 1) { if (t < o) red[t] += red[t+o]; __syncthreads(); }
    float inv = 1.f / red[0];
    c = 0;
    for (int j = t; j < NKV; j += 256) { s[j] = e[c] * inv; c++; }
}

// ---------------- O = P V ------------------------------------------------
__global__ void __launch_bounds__(256)
av_kernel() {
    int bt = blockIdx.x, h = blockIdx.y;
    __shared__ float Ps[32][133];
    __shared__ float Vs[32][96];
    int t = threadIdx.x, tx = t & 15, ty = t >> 4;

    float acc[8][6];
    #pragma unroll
    for (int i = 0; i < 8; i++)
        #pragma unroll
        for (int d = 0; d < 6; d++) acc[i][d] = 0.f;

    size_t prow0 = (size_t)(bt*NH + h) * NLAT;
    for (int jc = 0; jc < NKV; jc += 32) {
        for (int idx = t; idx < 128*32; idx += 256) {
            int i = idx >> 5, jj = idx & 31;
            Ps[jj][i] = g_s[(prow0 + i)*NKV + jc + jj];
        }
        for (int idx = t; idx < 32*96; idx += 256) {
            int jj = idx / 96, d = idx % 96;
            int j = jc + jj;
            float vv = (j < NMED)
                ? g_kvx[((size_t)(bt*NMED + j))*KV2 + INNER + h*DHEAD + d]
                : g_kvl[((size_t)(bt*NLAT + (j - NMED)))*KV2 + INNER + h*DHEAD + d];
            Vs[jj][d] = vv;
        }
        __syncthreads();
        #pragma unroll 8
        for (int jj = 0; jj < 32; jj++) {
            float ra[8], rb[6];
            #pragma unroll
            for (int i = 0; i < 8; i++) ra[i] = Ps[jj][ty*8 + i];
            #pragma unroll
            for (int d = 0; d < 6; d++) rb[d] = Vs[jj][tx + 16*d];
            #pragma unroll
            for (int i = 0; i < 8; i++)
                #pragma unroll
                for (int d = 0; d < 6; d++) acc[i][d] += ra[i]*rb[d];
        }
        __syncthreads();
    }

    #pragma unroll
    for (int i = 0; i < 8; i++)
        #pragma unroll
        for (int d = 0; d < 6; d++)
            g_o[((size_t)(bt*NLAT + ty*8 + i))*INNER + h*DHEAD + tx + 16*d] = acc[i][d];
}

// ---------------- host orchestration (graph-capturable) ------------------
extern "C" void kernel_launch(void* const* d_in, const int* in_sizes, int n_in,
                              void* d_out, int out_size) {
    (void)in_sizes; (void)n_in; (void)out_size;
    const float* x       = (const float*)d_in[0];
    const float* vmask   = (const float*)d_in[1];
    const float* latents = (const float*)d_in[2];
    const float* ln_m_g  = (const float*)d_in[3];
    const float* ln_m_b  = (const float*)d_in[4];
    const float* ln_l_g  = (const float*)d_in[5];
    const float* ln_l_b  = (const float*)d_in[6];
    const float* q_w     = (const float*)d_in[7];
    const float* kv_w    = (const float*)d_in[8];
    const float* out_w   = (const float*)d_in[9];
    const float* ff_ln_g = (const float*)d_in[10];
    const float* ff_ln_b = (const float*)d_in[11];
    const float* ff_w1   = (const float*)d_in[12];
    const float* ff_w2   = (const float*)d_in[13];
    const float* fn_g    = (const float*)d_in[14];
    const float* fn_b    = (const float*)d_in[15];
    float* out = (float*)d_out;

    float *p_lat, *p_lm, *p_xm, *p_q, *p_kvl, *p_kvx, *p_o, *p_h;
    float *p_qwT, *p_kvT, *p_outT, *p_ff1T, *p_ff2T;
    cudaGetSymbolAddress((void**)&p_lat, g_lat);
    cudaGetSymbolAddress((void**)&p_lm,  g_lm);
    cudaGetSymbolAddress((void**)&p_xm,  g_xm);
    cudaGetSymbolAddress((void**)&p_q,   g_q);
    cudaGetSymbolAddress((void**)&p_kvl, g_kvl);
    cudaGetSymbolAddress((void**)&p_kvx, g_kvx);
    cudaGetSymbolAddress((void**)&p_o,   g_o);
    cudaGetSymbolAddress((void**)&p_h,   g_h);
    cudaGetSymbolAddress((void**)&p_qwT,  g_qwT);
    cudaGetSymbolAddress((void**)&p_kvT,  g_kvT);
    cudaGetSymbolAddress((void**)&p_outT, g_outT);
    cudaGetSymbolAddress((void**)&p_ff1T, g_ff1T);
    cudaGetSymbolAddress((void**)&p_ff2T, g_ff2T);

    cudaFuncSetAttribute(tgemm<0>, cudaFuncAttributeMaxDynamicSharedMemorySize, SMEM_TG);
    cudaFuncSetAttribute(tgemm<1>, cudaFuncAttributeMaxDynamicSharedMemorySize, SMEM_TG);
    cudaFuncSetAttribute(tgemm<2>, cudaFuncAttributeMaxDynamicSharedMemorySize, SMEM_TG);

    const float scale = 1.0f / sqrtf((float)DHEAD);
    dim3 tb(32, 8);

    // pre-transpose all weights to K-major [N][K]
    transpose_kernel<<<dim3(INNER/32, DIMD/32, NLAYER), tb>>>(q_w,   p_qwT,  DIMD,  INNER);
    transpose_kernel<<<dim3(KV2/32,   DIMD/32, NLAYER), tb>>>(kv_w,  p_kvT,  DIMD,  KV2);
    transpose_kernel<<<dim3(DIMD/32, INNER/32, NLAYER), tb>>>(out_w, p_outT, INNER, DIMD);
    transpose_kernel<<<dim3(DFF/32,   DIMD/32, NLAYER), tb>>>(ff_w1, p_ff1T, DIMD,  DFF);
    transpose_kernel<<<dim3(DIMD/32,  DFF/32,  NLAYER), tb>>>(ff_w2, p_ff2T, DFF,   DIMD);

    bcast_kernel<<<RL*DIMD/256, 256>>>(latents);

    for (int l = 0; l < NLAYER; l++) {
        ln_kernel<<<XROWS, 256>>>(x,     ln_m_g + l*DIMD, ln_m_b + l*DIMD, p_xm);
        ln_kernel<<<RL,    256>>>(p_lat, ln_l_g + l*DIMD, ln_l_b + l*DIMD, p_lm);

        tgemm<0><<<dim3(INNER/128, RL/128),    256, SMEM_TG>>>(p_lm, p_qwT + (size_t)l*INNER*DIMD, p_q,   RL,    INNER, DIMD, scale);
        tgemm<0><<<dim3(KV2/128,   RL/128),    256, SMEM_TG>>>(p_lm, p_kvT + (size_t)l*KV2*DIMD,   p_kvl, RL,    KV2,   DIMD, 1.f);
        tgemm<0><<<dim3(KV2/128,   XROWS/128), 256, SMEM_TG>>>(p_xm, p_kvT + (size_t)l*KV2*DIMD,   p_kvx, XROWS, KV2,   DIMD, 1.f);

        scores_kernel<<<dim3(BT, NH, NKV/128), 256>>>(vmask);
        softmax_kernel<<<BT*NH*NLAT, 256>>>();
        av_kernel<<<dim3(BT, NH), 256>>>();

        tgemm<1><<<dim3(DIMD/128, RL/128), 256, SMEM_TG>>>(p_o, p_outT + (size_t)l*DIMD*INNER, p_lat, RL, DIMD, INNER, 1.f);

        ln_kernel<<<RL, 256>>>(p_lat, ff_ln_g + l*DIMD, ff_ln_b + l*DIMD, p_lm);
        tgemm<2><<<dim3(DFF/128,  RL/128), 256, SMEM_TG>>>(p_lm, p_ff1T + (size_t)l*DFF*DIMD, p_h,   RL, DFF,  DIMD, 1.f);
        tgemm<1><<<dim3(DIMD/128, RL/128), 256, SMEM_TG>>>(p_h,  p_ff2T + (size_t)l*DIMD*DFF, p_lat, RL, DIMD, DFF,  1.f);
    }

    ln_kernel<<<RL, 256>>>(p_lat, fn_g, fn_b, out);
}

// round 9
// speedup vs baseline: 1.9896x; 1.2884x over previous
#include <cuda_runtime.h>
#include <math.h>
#include <stdint.h>

#define NLAYER 6
#define NH     16
#define DHEAD  96
#define DIMD   1024
#define INNER  1536
#define DFF    4096
#define NLAT   128
#define BT     32                 /* b*T sites                */
#define NMED   1024               /* media tokens per site    */
#define XROWS  (BT*NMED)          /* 32768 media rows total   */
#define RL     (BT*NLAT)          /* 4096 latent rows total   */
#define NKV    (NMED+NLAT)        /* 1152 KV per site         */
#define KV2    (2*INNER)          /* 3072 */

// ---------------- scratch (device globals; no allocation) ----------------
__device__ float g_lat[(size_t)RL*DIMD];
__device__ float g_lm [(size_t)RL*DIMD];
__device__ float g_xm [(size_t)XROWS*DIMD];
__device__ float g_q  [(size_t)RL*INNER];
__device__ float g_kvl[(size_t)RL*KV2];
__device__ float g_kvx[(size_t)XROWS*KV2];
__device__ float g_o  [(size_t)RL*INNER];
__device__ float g_s  [(size_t)BT*NH*NLAT*NKV];
__device__ float g_h  [(size_t)RL*DFF];
__device__ int   g_cnt[8];
__device__ int   g_cidx[8*NMED];
// transposed weights (B operands K-major: [N][K])
__device__ float g_qwT [(size_t)NLAYER*INNER*DIMD];
__device__ float g_kvT [(size_t)NLAYER*KV2*DIMD];
__device__ float g_outT[(size_t)NLAYER*DIMD*INNER];
__device__ float g_ff1T[(size_t)NLAYER*DFF*DIMD];
__device__ float g_ff2T[(size_t)NLAYER*DIMD*DFF];

// ======================= PTX helpers =====================================
__device__ __forceinline__ uint32_t smem_u32(const void* p) {
    uint32_t r;
    asm("{ .reg .u64 t; cvta.to.shared.u64 t, %1; cvt.u32.u64 %0, t; }"
        : "=r"(r) : "l"(p));
    return r;
}

__device__ __forceinline__ void ldsm4(uint32_t* r, uint32_t a) {
    asm volatile("ldmatrix.sync.aligned.m8n8.x4.shared.b16 {%0,%1,%2,%3}, [%4];"
        : "=r"(r[0]), "=r"(r[1]), "=r"(r[2]), "=r"(r[3]) : "r"(a));
}
__device__ __forceinline__ void ldsm2(uint32_t* r, uint32_t a) {
    asm volatile("ldmatrix.sync.aligned.m8n8.x2.shared.b16 {%0,%1}, [%2];"
        : "=r"(r[0]), "=r"(r[1]) : "r"(a));
}
__device__ __forceinline__ void mma16816(float* c, const uint32_t* a, const uint32_t* b) {
    asm volatile("mma.sync.aligned.m16n8k16.row.col.f32.bf16.bf16.f32 "
        "{%0,%1,%2,%3}, {%4,%5,%6,%7}, {%8,%9}, {%0,%1,%2,%3};"
        : "+f"(c[0]), "+f"(c[1]), "+f"(c[2]), "+f"(c[3])
        : "r"(a[0]), "r"(a[1]), "r"(a[2]), "r"(a[3]), "r"(b[0]), "r"(b[1]));
}

// ======================= bf16x3 tensor-core GEMM =========================
// C[M,N] = epi(alpha * A[M,K] @ Bt[N,K]^T).  M,N multiples of 128; K of 32.
// EPI: 0 = alpha* ; 1 = C += ; 2 = gelu_exact
// CNT_SKIP: blockIdx.y maps to (bt-slot of 8 tiles); skip tile if beyond cnt.
#define ROWB   80
#define T_AHI  0
#define T_ALO  10240
#define T_BHI  20480
#define T_BLO  30720
#define STGSZ  40960
#define SMEM_TG (2*STGSZ)

template<int EPI, int CNT_SKIP>
__global__ void __launch_bounds__(256, 1)
tgemm(const float* __restrict__ A, const float* __restrict__ Bt,
      float* __restrict__ C, int M, int N, int K, float alpha) {
    if (CNT_SKIP) {
        int by = blockIdx.y;                 // bt = by>>3, tile = by&7
        int b  = by >> 5;                    // (by>>3)>>2
        if ((by & 7) * 128 >= g_cnt[b]) return;
    }
    extern __shared__ char smem[];
    const uint32_t sb = smem_u32(smem);
    const int t = threadIdx.x;
    const int lane = t & 31, wid = t >> 5;
    const int wm = (wid >> 2) * 64;
    const int wn = (wid & 3) * 32;
    const int m0 = blockIdx.y * 128, n0 = blockIdx.x * 128;

    const float* Ab = A  + (size_t)m0 * K;
    const float* Bb = Bt + (size_t)n0 * K;

    float acc[4][4][4];
    #pragma unroll
    for (int i = 0; i < 4; i++)
        #pragma unroll
        for (int j = 0; j < 4; j++)
            #pragma unroll
            for (int r = 0; r < 4; r++) acc[i][j][r] = 0.f;

    const int nch = K / 32;

    auto stage = [&](int c, int buf) {
        char* st = smem + buf * STGSZ;
        #pragma unroll
        for (int j = 0; j < 4; j++) {
            int idx = t + 256 * j;
            int row = idx >> 3, q = idx & 7;
            float4 v = *(const float4*)(Ab + (size_t)row * K + c * 32 + q * 4);
            uint32_t h01 = __byte_perm(__float_as_uint(v.x), __float_as_uint(v.y), 0x7632);
            uint32_t h23 = __byte_perm(__float_as_uint(v.z), __float_as_uint(v.w), 0x7632);
            float lx = v.x - __uint_as_float(__float_as_uint(v.x) & 0xFFFF0000u);
            float ly = v.y - __uint_as_float(__float_as_uint(v.y) & 0xFFFF0000u);
            float lz = v.z - __uint_as_float(__float_as_uint(v.z) & 0xFFFF0000u);
            float lw = v.w - __uint_as_float(__float_as_uint(v.w) & 0xFFFF0000u);
            uint32_t l01, l23;
            asm("cvt.rn.bf16x2.f32 %0, %1, %2;" : "=r"(l01) : "f"(ly), "f"(lx));
            asm("cvt.rn.bf16x2.f32 %0, %1, %2;" : "=r"(l23) : "f"(lw), "f"(lz));
            *(uint2*)(st + T_AHI + row * ROWB + q * 8) = make_uint2(h01, h23);
            *(uint2*)(st + T_ALO + row * ROWB + q * 8) = make_uint2(l01, l23);
            v = *(const float4*)(Bb + (size_t)row * K + c * 32 + q * 4);
            h01 = __byte_perm(__float_as_uint(v.x), __float_as_uint(v.y), 0x7632);
            h23 = __byte_perm(__float_as_uint(v.z), __float_as_uint(v.w), 0x7632);
            lx = v.x - __uint_as_float(__float_as_uint(v.x) & 0xFFFF0000u);
            ly = v.y - __uint_as_float(__float_as_uint(v.y) & 0xFFFF0000u);
            lz = v.z - __uint_as_float(__float_as_uint(v.z) & 0xFFFF0000u);
            lw = v.w - __uint_as_float(__float_as_uint(v.w) & 0xFFFF0000u);
            asm("cvt.rn.bf16x2.f32 %0, %1, %2;" : "=r"(l01) : "f"(ly), "f"(lx));
            asm("cvt.rn.bf16x2.f32 %0, %1, %2;" : "=r"(l23) : "f"(lw), "f"(lz));
            *(uint2*)(st + T_BHI + row * ROWB + q * 8) = make_uint2(h01, h23);
            *(uint2*)(st + T_BLO + row * ROWB + q * 8) = make_uint2(l01, l23);
        }
    };

    const int arow  = wm + (lane & 7) + ((lane >> 3) & 1) * 8;
    const int akoff = ((lane >> 4) & 1) * 16;
    const int brow  = wn + (lane & 7);
    const int bkoff = ((lane >> 3) & 1) * 16;

    stage(0, 0);
    __syncthreads();

    for (int c = 0; c < nch; c++) {
        if (c + 1 < nch) stage(c + 1, (c + 1) & 1);
        const uint32_t base = sb + (c & 1) * STGSZ;
        #pragma unroll
        for (int ks = 0; ks < 2; ks++) {
            uint32_t ah[4][4], al[4][4], bh[4][2], bl[4][2];
            #pragma unroll
            for (int mt = 0; mt < 4; mt++) {
                uint32_t ad = base + (uint32_t)(arow + mt * 16) * ROWB + ks * 32 + akoff;
                ldsm4(ah[mt], ad + T_AHI);
                ldsm4(al[mt], ad + T_ALO);
            }
            #pragma unroll
            for (int nt = 0; nt < 4; nt++) {
                uint32_t bd = base + (uint32_t)(brow + nt * 8) * ROWB + ks * 32 + bkoff;
                ldsm2(bh[nt], bd + T_BHI);
                ldsm2(bl[nt], bd + T_BLO);
            }
            #pragma unroll
            for (int mt = 0; mt < 4; mt++)
                #pragma unroll
                for (int nt = 0; nt < 4; nt++) {
                    mma16816(acc[mt][nt], ah[mt], bh[nt]);
                    mma16816(acc[mt][nt], ah[mt], bl[nt]);
                    mma16816(acc[mt][nt], al[mt], bh[nt]);
                }
        }
        __syncthreads();
    }

    const int rl = lane >> 2;
    const int cl = (lane & 3) * 2;
    #pragma unroll
    for (int mt = 0; mt < 4; mt++) {
        #pragma unroll
        for (int nt = 0; nt < 4; nt++) {
            int gr = m0 + wm + mt * 16 + rl;
            int gc = n0 + wn + nt * 8 + cl;
            float* p0 = C + (size_t)gr * N + gc;
            float* p1 = C + (size_t)(gr + 8) * N + gc;
            float2 v0 = make_float2(acc[mt][nt][0] * alpha, acc[mt][nt][1] * alpha);
            float2 v1 = make_float2(acc[mt][nt][2] * alpha, acc[mt][nt][3] * alpha);
            if (EPI == 1) {
                float2 c0 = *(float2*)p0, c1 = *(float2*)p1;
                v0.x += c0.x; v0.y += c0.y; v1.x += c1.x; v1.y += c1.y;
            }
            if (EPI == 2) {
                v0.x = 0.5f * v0.x * (1.0f + erff(v0.x * 0.70710678118654752f));
                v0.y = 0.5f * v0.y * (1.0f + erff(v0.y * 0.70710678118654752f));
                v1.x = 0.5f * v1.x * (1.0f + erff(v1.x * 0.70710678118654752f));
                v1.y = 0.5f * v1.y * (1.0f + erff(v1.y * 0.70710678118654752f));
            }
            *(float2*)p0 = v0;
            *(float2*)p1 = v1;
        }
    }
}

// ---------------- mask compaction: one block (1024 thr) per b ------------
__global__ void compact_kernel(const float* __restrict__ vmask) {
    int b = blockIdx.x, t = threadIdx.x;
    __shared__ int woff[32];
    int valid = (vmask[b * NMED + t] > 0.f) ? 1 : 0;
    unsigned bal = __ballot_sync(0xffffffffu, valid);
    int lane = t & 31, wid = t >> 5;
    int pre = __popc(bal & ((1u << lane) - 1u));
    if (lane == 31) woff[wid] = __popc(bal);
    __syncthreads();
    if (t == 0) {
        int s = 0;
        #pragma unroll
        for (int w = 0; w < 32; w++) { int c = woff[w]; woff[w] = s; s += c; }
        g_cnt[b] = s;
    }
    __syncthreads();
    if (valid) g_cidx[b * NMED + woff[wid] + pre] = t;
}

// ---------------- weight transpose ---------------------------------------
__global__ void transpose_kernel(const float* __restrict__ src,
                                 float* __restrict__ dst, int R, int Ccols) {
    __shared__ float tile[32][33];
    size_t zoff = (size_t)blockIdx.z * R * Ccols;
    int r0 = blockIdx.y * 32, c0 = blockIdx.x * 32;
    int tx = threadIdx.x, ty = threadIdx.y;
    #pragma unroll
    for (int i = ty; i < 32; i += 8)
        tile[i][tx] = src[zoff + (size_t)(r0 + i) * Ccols + c0 + tx];
    __syncthreads();
    #pragma unroll
    for (int i = ty; i < 32; i += 8)
        dst[zoff + (size_t)(c0 + i) * R + r0 + tx] = tile[tx][i];
}

// ---------------- broadcast latents --------------------------------------
__global__ void bcast_kernel(const float* __restrict__ lat) {
    int i = blockIdx.x * 256 + threadIdx.x;
    int row = i >> 10;
    int col = i & 1023;
    g_lat[i] = lat[((row & (NLAT-1)) << 10) + col];
}

// ---------------- LayerNorm (generic) ------------------------------------
__device__ __forceinline__ void ln_row(const float* __restrict__ x,
                                       const float* __restrict__ gg,
                                       const float* __restrict__ bb,
                                       float* __restrict__ y, int t,
                                       float* red) {
    float v[4]; float s = 0.f;
    #pragma unroll
    for (int i = 0; i < 4; i++) { v[i] = x[t + 256*i]; s += v[i]; }
    red[t] = s; __syncthreads();
    #pragma unroll
    for (int o = 128; o > 0; o >>= 1) { if (t < o) red[t] += red[t+o]; __syncthreads(); }
    float mu = red[0] * (1.f/DIMD);
    __syncthreads();
    float s2 = 0.f;
    #pragma unroll
    for (int i = 0; i < 4; i++) { float d = v[i]-mu; s2 += d*d; }
    red[t] = s2; __syncthreads();
    #pragma unroll
    for (int o = 128; o > 0; o >>= 1) { if (t < o) red[t] += red[t+o]; __syncthreads(); }
    float inv = rsqrtf(red[0]*(1.f/DIMD) + 1e-5f);
    #pragma unroll
    for (int i = 0; i < 4; i++) { int c = t + 256*i; y[c] = (v[i]-mu)*inv*gg[c] + bb[c]; }
}

__global__ void ln_kernel(const float* __restrict__ in,
                          const float* __restrict__ gg,
                          const float* __restrict__ bb,
                          float* __restrict__ out) {
    __shared__ float red[256];
    int row = blockIdx.x;
    ln_row(in + (size_t)row * DIMD, gg, bb, out + (size_t)row * DIMD,
           threadIdx.x, red);
}

// media LN with compaction gather: dst row (bt, i) <- x row (bt, cidx[b][i])
__global__ void ln_media_kernel(const float* __restrict__ x,
                                const float* __restrict__ gg,
                                const float* __restrict__ bb) {
    int r = blockIdx.x;                 // 0..XROWS-1
    int bt = r >> 10, i = r & (NMED-1);
    int b = bt >> 2;
    if (i >= g_cnt[b]) return;
    int src = (bt << 10) + g_cidx[b * NMED + i];
    __shared__ float red[256];
    ln_row(x + (size_t)src * DIMD, gg, bb, g_xm + (size_t)r * DIMD,
           threadIdx.x, red);
}

// ---- scores: block = (bt, h, jt); compacted media + latents -------------
__global__ void __launch_bounds__(256)
scores_kernel() {
    int bt = blockIdx.x, h = blockIdx.y, jt = blockIdx.z;
    int b  = bt >> 2;
    int j0 = jt * 128;
    int t = threadIdx.x;
    int cnt = g_cnt[b];
    size_t base = ((size_t)(bt*NH + h)) * NLAT;

    if (j0 < NMED && j0 >= cnt) {       // fully padded media tile: -inf
        for (int idx = t; idx < 128*128; idx += 256) {
            int i = idx >> 7, j = idx & 127;
            g_s[(base + i)*NKV + j0 + j] = -INFINITY;
        }
        return;
    }

    __shared__ float Qs[32][129];
    __shared__ float Ks[32][129];
    int tx = t & 15, ty = t >> 4;

    float acc[8][8];
    #pragma unroll
    for (int i = 0; i < 8; i++)
        #pragma unroll
        for (int j = 0; j < 8; j++) acc[i][j] = 0.f;

    for (int dc = 0; dc < DHEAD; dc += 32) {
        for (int idx = t; idx < 128*32; idx += 256) {
            int i = idx >> 5, d = idx & 31;
            Qs[d][i] = g_q[((size_t)(bt*NLAT + i))*INNER + h*DHEAD + dc + d];
        }
        for (int idx = t; idx < 128*32; idx += 256) {
            int jj = idx >> 5, d = idx & 31;
            int j = j0 + jj;
            float kv = (j < NMED)
                ? g_kvx[((size_t)(bt*NMED + j))*KV2 + h*DHEAD + dc + d]
                : g_kvl[((size_t)(bt*NLAT + (j - NMED)))*KV2 + h*DHEAD + dc + d];
            Ks[d][jj] = kv;
        }
        __syncthreads();
        #pragma unroll 8
        for (int d = 0; d < 32; d++) {
            float ra[8], rb[8];
            #pragma unroll
            for (int i = 0; i < 8; i++) ra[i] = Qs[d][ty*8 + i];
            #pragma unroll
            for (int j = 0; j < 4; j++) { rb[j] = Ks[d][tx*4 + j]; rb[j+4] = Ks[d][64 + tx*4 + j]; }
            #pragma unroll
            for (int i = 0; i < 8; i++)
                #pragma unroll
                for (int j = 0; j < 8; j++) acc[i][j] += ra[i]*rb[j];
        }
        __syncthreads();
    }

    #pragma unroll
    for (int i = 0; i < 8; i++) {
        int row = ty*8 + i;
        #pragma unroll
        for (int j = 0; j < 8; j++) {
            int cc = (j < 4) ? (tx*4 + j) : (64 + tx*4 + j - 4);
            int jg = j0 + cc;
            float v = acc[i][j];
            if (jg < NMED && jg >= cnt) v = -INFINITY;
            g_s[(base + row)*NKV + jg] = v;
        }
    }
}

// ---------------- softmax over 1152 KV -----------------------------------
__global__ void softmax_kernel() {
    size_t row = blockIdx.x;
    float* s = g_s + row * (size_t)NKV;
    int t = threadIdx.x;
    __shared__ float red[256];
    float m = -INFINITY;
    for (int j = t; j < NKV; j += 256) m = fmaxf(m, s[j]);
    red[t] = m; __syncthreads();
    #pragma unroll
    for (int o = 128; o > 0; o >>= 1) { if (t < o) red[t] = fmaxf(red[t], red[t+o]); __syncthreads(); }
    m = red[0]; __syncthreads();
    float e[5]; int c = 0; float sum = 0.f;
    for (int j = t; j < NKV; j += 256) { e[c] = expf(s[j] - m); sum += e[c]; c++; }
    red[t] = sum; __syncthreads();
    #pragma unroll
    for (int o = 128; o > 0; o >>= 1) { if (t < o) red[t] += red[t+o]; __syncthreads(); }
    float inv = 1.f / red[0];
    c = 0;
    for (int j = t; j < NKV; j += 256) { s[j] = e[c] * inv; c++; }
}

// ---------------- O = P V ------------------------------------------------
__global__ void __launch_bounds__(256)
av_kernel() {
    int bt = blockIdx.x, h = blockIdx.y;
    int b = bt >> 2;
    int cnt = g_cnt[b];
    __shared__ float Ps[32][133];
    __shared__ float Vs[32][96];
    int t = threadIdx.x, tx = t & 15, ty = t >> 4;

    float acc[8][6];
    #pragma unroll
    for (int i = 0; i < 8; i++)
        #pragma unroll
        for (int d = 0; d < 6; d++) acc[i][d] = 0.f;

    size_t prow0 = (size_t)(bt*NH + h) * NLAT;
    for (int jc = 0; jc < NKV; jc += 32) {
        // skip fully-masked media chunks (probs exactly 0 there)
        if (jc < NMED && jc >= cnt) continue;
        for (int idx = t; idx < 128*32; idx += 256) {
            int i = idx >> 5, jj = idx & 31;
            Ps[jj][i] = g_s[(prow0 + i)*NKV + jc + jj];
        }
        for (int idx = t; idx < 32*96; idx += 256) {
            int jj = idx / 96, d = idx % 96;
            int j = jc + jj;
            float vv;
            if (j < NMED) {
                vv = (j < cnt) ? g_kvx[((size_t)(bt*NMED + j))*KV2 + INNER + h*DHEAD + d] : 0.f;
            } else {
                vv = g_kvl[((size_t)(bt*NLAT + (j - NMED)))*KV2 + INNER + h*DHEAD + d];
            }
            Vs[jj][d] = vv;
        }
        __syncthreads();
        #pragma unroll 8
        for (int jj = 0; jj < 32; jj++) {
            float ra[8], rb[6];
            #pragma unroll
            for (int i = 0; i < 8; i++) ra[i] = Ps[jj][ty*8 + i];
            #pragma unroll
            for (int d = 0; d < 6; d++) rb[d] = Vs[jj][tx + 16*d];
            #pragma unroll
            for (int i = 0; i < 8; i++)
                #pragma unroll
                for (int d = 0; d < 6; d++) acc[i][d] += ra[i]*rb[d];
        }
        __syncthreads();
    }

    #pragma unroll
    for (int i = 0; i < 8; i++)
        #pragma unroll
        for (int d = 0; d < 6; d++)
            g_o[((size_t)(bt*NLAT + ty*8 + i))*INNER + h*DHEAD + tx + 16*d] = acc[i][d];
}

// ---------------- host orchestration (graph-capturable) ------------------
extern "C" void kernel_launch(void* const* d_in, const int* in_sizes, int n_in,
                              void* d_out, int out_size) {
    (void)in_sizes; (void)n_in; (void)out_size;
    const float* x       = (const float*)d_in[0];
    const float* vmask   = (const float*)d_in[1];
    const float* latents = (const float*)d_in[2];
    const float* ln_m_g  = (const float*)d_in[3];
    const float* ln_m_b  = (const float*)d_in[4];
    const float* ln_l_g  = (const float*)d_in[5];
    const float* ln_l_b  = (const float*)d_in[6];
    const float* q_w     = (const float*)d_in[7];
    const float* kv_w    = (const float*)d_in[8];
    const float* out_w   = (const float*)d_in[9];
    const float* ff_ln_g = (const float*)d_in[10];
    const float* ff_ln_b = (const float*)d_in[11];
    const float* ff_w1   = (const float*)d_in[12];
    const float* ff_w2   = (const float*)d_in[13];
    const float* fn_g    = (const float*)d_in[14];
    const float* fn_b    = (const float*)d_in[15];
    float* out = (float*)d_out;

    float *p_lat, *p_lm, *p_xm, *p_q, *p_kvl, *p_kvx, *p_o, *p_h;
    float *p_qwT, *p_kvT, *p_outT, *p_ff1T, *p_ff2T;
    cudaGetSymbolAddress((void**)&p_lat, g_lat);
    cudaGetSymbolAddress((void**)&p_lm,  g_lm);
    cudaGetSymbolAddress((void**)&p_xm,  g_xm);
    cudaGetSymbolAddress((void**)&p_q,   g_q);
    cudaGetSymbolAddress((void**)&p_kvl, g_kvl);
    cudaGetSymbolAddress((void**)&p_kvx, g_kvx);
    cudaGetSymbolAddress((void**)&p_o,   g_o);
    cudaGetSymbolAddress((void**)&p_h,   g_h);
    cudaGetSymbolAddress((void**)&p_qwT,  g_qwT);
    cudaGetSymbolAddress((void**)&p_kvT,  g_kvT);
    cudaGetSymbolAddress((void**)&p_outT, g_outT);
    cudaGetSymbolAddress((void**)&p_ff1T, g_ff1T);
    cudaGetSymbolAddress((void**)&p_ff2T, g_ff2T);

    cudaFuncSetAttribute((const void*)tgemm<0,0>, cudaFuncAttributeMaxDynamicSharedMemorySize, SMEM_TG);
    cudaFuncSetAttribute((const void*)tgemm<0,1>, cudaFuncAttributeMaxDynamicSharedMemorySize, SMEM_TG);
    cudaFuncSetAttribute((const void*)tgemm<1,0>, cudaFuncAttributeMaxDynamicSharedMemorySize, SMEM_TG);
    cudaFuncSetAttribute((const void*)tgemm<2,0>, cudaFuncAttributeMaxDynamicSharedMemorySize, SMEM_TG);

    const float scale = 1.0f / sqrtf((float)DHEAD);
    dim3 tb(32, 8);

    // pre-transpose all weights to K-major [N][K]
    transpose_kernel<<<dim3(INNER/32, DIMD/32, NLAYER), tb>>>(q_w,   p_qwT,  DIMD,  INNER);
    transpose_kernel<<<dim3(KV2/32,   DIMD/32, NLAYER), tb>>>(kv_w,  p_kvT,  DIMD,  KV2);
    transpose_kernel<<<dim3(DIMD/32, INNER/32, NLAYER), tb>>>(out_w, p_outT, INNER, DIMD);
    transpose_kernel<<<dim3(DFF/32,   DIMD/32, NLAYER), tb>>>(ff_w1, p_ff1T, DIMD,  DFF);
    transpose_kernel<<<dim3(DIMD/32,  DFF/32,  NLAYER), tb>>>(ff_w2, p_ff2T, DFF,   DIMD);

    compact_kernel<<<8, 1024>>>(vmask);
    bcast_kernel<<<RL*DIMD/256, 256>>>(latents);

    for (int l = 0; l < NLAYER; l++) {
        ln_media_kernel<<<XROWS, 256>>>(x, ln_m_g + l*DIMD, ln_m_b + l*DIMD);
        ln_kernel<<<RL, 256>>>(p_lat, ln_l_g + l*DIMD, ln_l_b + l*DIMD, p_lm);

        tgemm<0,0><<<dim3(INNER/128, RL/128),    256, SMEM_TG>>>(p_lm, p_qwT + (size_t)l*INNER*DIMD, p_q,   RL,    INNER, DIMD, scale);
        tgemm<0,0><<<dim3(KV2/128,   RL/128),    256, SMEM_TG>>>(p_lm, p_kvT + (size_t)l*KV2*DIMD,   p_kvl, RL,    KV2,   DIMD, 1.f);
        tgemm<0,1><<<dim3(KV2/128,   XROWS/128), 256, SMEM_TG>>>(p_xm, p_kvT + (size_t)l*KV2*DIMD,   p_kvx, XROWS, KV2,   DIMD, 1.f);

        scores_kernel<<<dim3(BT, NH, NKV/128), 256>>>();
        softmax_kernel<<<BT*NH*NLAT, 256>>>();
        av_kernel<<<dim3(BT, NH), 256>>>();

        tgemm<1,0><<<dim3(DIMD/128, RL/128), 256, SMEM_TG>>>(p_o, p_outT + (size_t)l*DIMD*INNER, p_lat, RL, DIMD, INNER, 1.f);

        ln_kernel<<<RL, 256>>>(p_lat, ff_ln_g + l*DIMD, ff_ln_b + l*DIMD, p_lm);
        tgemm<2,0><<<dim3(DFF/128,  RL/128), 256, SMEM_TG>>>(p_lm, p_ff1T + (size_t)l*DFF*DIMD, p_h,   RL, DFF,  DIMD, 1.f);
        tgemm<1,0><<<dim3(DIMD/128, RL/128), 256, SMEM_TG>>>(p_h,  p_ff2T + (size_t)l*DIMD*DFF, p_lat, RL, DIMD, DFF,  1.f);
    }

    ln_kernel<<<RL, 256>>>(p_lat, fn_g, fn_b, out);
}